// round 4
// baseline (speedup 1.0000x reference)
#include <cuda_runtime.h>
#include <cuda_bf16.h>
#include <math.h>
#include <stdint.h>

#define D_IN   1024
#define D_H    2048
#define BATCH  256
#define D_OUT  1000
#define ALPHA  0.5f
#define EPSV   1e-12f
#define STEPS  30

// tcgen05 is an arch-SPECIFIC feature: only present when compiling the
// sm_103a/sm_100a cubin pass. The harness also runs a portable compute_103
// PTX pass where these instructions do not exist — that pass gets a plain
// FFMA fallback body instead.
#if defined(__CUDA_ARCH_FEAT_SM103_ALL) || defined(__CUDA_ARCH_FEAT_SM100_ALL) || defined(__CUDA_ARCH_FEAT_SM101_ALL)
#define TC_OK 1
#else
#define TC_OK 0
#endif

// ---------------- device scratch (no allocations allowed) ----------------
__device__ float g_t[D_IN];
__device__ float g_s[D_H];
__device__ float g_scal[4];            // [1] = 1/sigma
__device__ float g_xproj[BATCH * D_H];
__device__ float g_hA[BATCH * D_H];
__device__ float g_hB[BATCH * D_H];

// bf16 hi/lo splits
__device__ __nv_bfloat16 g_W0hi[D_H * D_H], g_W0lo[D_H * D_H];
__device__ __nv_bfloat16 g_W1hi[D_H * D_H], g_W1lo[D_H * D_H];
__device__ __nv_bfloat16 g_W2hi[D_H * D_H], g_W2lo[D_H * D_H];
__device__ __nv_bfloat16 g_Winhi[D_H * D_IN], g_Winlo[D_H * D_IN];
__device__ __nv_bfloat16 g_Hdhi[D_OUT * D_H], g_Hdlo[D_OUT * D_H];
__device__ __nv_bfloat16 g_xhi[BATCH * D_IN], g_xlo[BATCH * D_IN];
__device__ __nv_bfloat16 g_hhiA[BATCH * D_H], g_hloA[BATCH * D_H];
__device__ __nv_bfloat16 g_hhiB[BATCH * D_H], g_hloB[BATCH * D_H];

// ---------------- PTX helpers ----------------
__device__ __forceinline__ uint32_t smem_u32(const void* p) {
    uint32_t a;
    asm("{ .reg .u64 t; cvta.to.shared.u64 t, %1; cvt.u32.u64 %0, t; }" : "=r"(a) : "l"(p));
    return a;
}

#if TC_OK
__device__ __forceinline__ uint32_t elect_one() {
    uint32_t p;
    asm volatile("{ .reg .pred p; elect.sync _|p, 0xFFFFFFFF; selp.b32 %0, 1, 0, p; }" : "=r"(p));
    return p;
}
#define TC_ALLOC(slot, n)  asm volatile("tcgen05.alloc.cta_group::1.sync.aligned.shared::cta.b32 [%0], %1;" :: "r"(slot), "r"(n) : "memory")
#define TC_DEALLOC(tm, n)  asm volatile("tcgen05.dealloc.cta_group::1.sync.aligned.b32 %0, %1;" :: "r"(tm), "r"(n))
#define TC_RELINQ()        asm volatile("tcgen05.relinquish_alloc_permit.cta_group::1.sync.aligned;")
#define TC_COMMIT(mbar)    asm volatile("tcgen05.commit.cta_group::1.mbarrier::arrive::one.shared::cluster.b64 [%0];" :: "r"(mbar) : "memory")
#define TC_FENCE_AFTER()   asm volatile("tcgen05.fence::after_thread_sync;" ::: "memory")
#define TC_FENCE_BEFORE()  asm volatile("tcgen05.fence::before_thread_sync;" ::: "memory")
#define TC_WAIT_LD()       asm volatile("tcgen05.wait::ld.sync.aligned;" ::: "memory")
#define MBAR_INIT(a, c)    asm volatile("mbarrier.init.shared.b64 [%0], %1;" :: "r"(a), "r"(c) : "memory")
#define FENCE_ASYNC()      asm volatile("fence.proxy.async.shared::cta;" ::: "memory")

#define MBAR_WAIT(mbar, parity) do {                                              \
    uint32_t _m = (mbar), _p = (parity), _d;                                      \
    asm volatile("{ .reg .pred p; mbarrier.try_wait.parity.acquire.cta.shared::cta.b64 p, [%1], %2; selp.b32 %0, 1, 0, p; }" \
        : "=r"(_d) : "r"(_m), "r"(_p) : "memory");                                \
    if (!_d) {                                                                    \
        asm volatile("{ .reg .pred P1; WL_%=: mbarrier.try_wait.parity.acquire.cta.shared::cta.b64 P1, [%0], %1, 0x989680; @P1 bra.uni WD_%=; bra.uni WL_%=; WD_%=: }" \
            :: "r"(_m), "r"(_p) : "memory");                                      \
    }                                                                             \
} while (0)

#define LDTM_X32(r, tm)                                                           \
    asm volatile("tcgen05.ld.sync.aligned.32x32b.x32.b32 "                        \
        "{%0,%1,%2,%3,%4,%5,%6,%7,%8,%9,%10,%11,%12,%13,%14,%15,"                 \
        "%16,%17,%18,%19,%20,%21,%22,%23,%24,%25,%26,%27,%28,%29,%30,%31}, [%32];" \
        : "=r"((r)[0]),"=r"((r)[1]),"=r"((r)[2]),"=r"((r)[3]),"=r"((r)[4]),"=r"((r)[5]),"=r"((r)[6]),"=r"((r)[7]), \
          "=r"((r)[8]),"=r"((r)[9]),"=r"((r)[10]),"=r"((r)[11]),"=r"((r)[12]),"=r"((r)[13]),"=r"((r)[14]),"=r"((r)[15]), \
          "=r"((r)[16]),"=r"((r)[17]),"=r"((r)[18]),"=r"((r)[19]),"=r"((r)[20]),"=r"((r)[21]),"=r"((r)[22]),"=r"((r)[23]), \
          "=r"((r)[24]),"=r"((r)[25]),"=r"((r)[26]),"=r"((r)[27]),"=r"((r)[28]),"=r"((r)[29]),"=r"((r)[30]),"=r"((r)[31]) \
        : "r"(tm))

// SS-mode bf16 MMA, cg1: D[128xN] += A_smem @ B_smem^T
__device__ __forceinline__ void mma_f16_ss(uint32_t d, uint64_t ad, uint64_t bd,
                                           uint32_t idesc, uint32_t en) {
    asm volatile(
        "{ .reg .pred p; setp.ne.u32 p, %5, 0;\n\t"
        "tcgen05.mma.cta_group::1.kind::f16 [%0], %1, %2, %3, {%4,%4,%4,%4}, p; }"
        :: "r"(d), "l"(ad), "l"(bd), "r"(idesc), "r"(0u), "r"(en) : "memory");
}

// SW128 K-major descriptor: layout=2, version=1, SBO=64, LBO=1
__device__ __forceinline__ uint64_t make_desc(uint32_t addr) {
    const uint64_t base = (uint64_t(2) << 61) | (uint64_t(1) << 46) |
                          (uint64_t(64) << 32) | (uint64_t(1) << 16);
    return base | ((uint64_t)(addr >> 4) & 0x3FFF);
}

// idesc kind::f16: dtype F32(1<<4), atype BF16(1<<7), btype BF16(1<<10), N=64(8<<17), M=128(8<<24)
#define IDESC_128x64 0x8100490u
#endif  // TC_OK

// ---------------- small kernels ----------------
__global__ void zero_kernel(float* p, int n) {
    int i = blockIdx.x * blockDim.x + threadIdx.x;
    if (i < n) p[i] = 0.0f;
}

__global__ void split_kernel(const float* __restrict__ src,
                             __nv_bfloat16* __restrict__ hi,
                             __nv_bfloat16* __restrict__ lo, int n) {
    int i = blockIdx.x * blockDim.x + threadIdx.x;
    if (i >= n) return;
    float a = src[i];
    __nv_bfloat16 h = __float2bfloat16(a);
    hi[i] = h;
    lo[i] = __float2bfloat16(a - __bfloat162float(h));
}

__global__ void matvec_t_kernel(const float* __restrict__ W, const float* __restrict__ u,
                                float* __restrict__ t) {
    int j = blockIdx.x * blockDim.x + threadIdx.x;
    if (j >= D_IN) return;
    float acc = 0.0f;
#pragma unroll 4
    for (int i = 0; i < D_H; i++) acc = fmaf(W[(size_t)i * D_IN + j], u[i], acc);
    t[j] = acc;
}
__global__ void reduce_t_kernel(const float* __restrict__ t, float* __restrict__ scal) {
    __shared__ float sh[1024];
    int tid = threadIdx.x;
    float v = t[tid];
    sh[tid] = v * v;
    __syncthreads();
    for (int o = 512; o > 0; o >>= 1) { if (tid < o) sh[tid] += sh[tid + o]; __syncthreads(); }
    if (tid == 0) scal[0] = 1.0f / (sqrtf(sh[0]) + EPSV);
}
__global__ void matvec_s_kernel(const float* __restrict__ W, const float* __restrict__ t,
                                const float* __restrict__ scal, float* __restrict__ s) {
    int gtid = blockIdx.x * blockDim.x + threadIdx.x;
    int warp = gtid >> 5, lane = gtid & 31;
    float invn = scal[0];
    for (int r = warp; r < D_H; r += 512) {
        const float* row = W + (size_t)r * D_IN;
        float acc = 0.0f;
        for (int j = lane; j < D_IN; j += 32) acc = fmaf(row[j], t[j], acc);
#pragma unroll
        for (int o = 16; o > 0; o >>= 1) acc += __shfl_xor_sync(0xffffffffu, acc, o);
        if (lane == 0) s[r] = acc * invn;
    }
}
__global__ void reduce_s_kernel(const float* __restrict__ s, float* __restrict__ scal) {
    __shared__ float sh[1024];
    int tid = threadIdx.x;
    float a = s[tid], b = s[tid + 1024];
    sh[tid] = a * a + b * b;
    __syncthreads();
    for (int o = 512; o > 0; o >>= 1) { if (tid < o) sh[tid] += sh[tid + o]; __syncthreads(); }
    if (tid == 0) { float q = sh[0]; scal[1] = (sqrtf(q) + EPSV) / q; }
}

// ---------------- GEMM: C = (Ahi+Alo)(Bhi+Blo)^T, lo*lo dropped ----------------
// MODE 0: outF = acc * (*scale_ptr) + bias[n]                        (x_proj)
// MODE 1: hn = 0.5*hold + 0.5*tanh(xproj + acc + bias); outF=hn; outHi/Lo=split(hn)
// MODE 2: outF = acc + bias[n]   (guard n < NB)                      (head)
// SMEM: [0..16) mbar[2], [16..20) tmem ptr, stage s at 1024 + s*49152:
//   A_hi +0 (16KB), A_lo +16K, B_hi +32K (8KB), B_lo +40K (8KB)
#define SMEM_BYTES 99328
#define STAGE_SZ   49152

__device__ __forceinline__ void load_chunk(char* sb, int k0,
        const __nv_bfloat16* __restrict__ Ahi, const __nv_bfloat16* __restrict__ Alo,
        const __nv_bfloat16* __restrict__ Bhi, const __nv_bfloat16* __restrict__ Blo,
        int K, int NB, int m0, int n0) {
    const int t = threadIdx.x;
    // A: thread t loads row t (hi + lo), 64 bf16 = 8x uint4, SW128 swizzle
    {
        const uint4* sH = reinterpret_cast<const uint4*>(Ahi + (size_t)(m0 + t) * K + k0);
        const uint4* sL = reinterpret_cast<const uint4*>(Alo + (size_t)(m0 + t) * K + k0);
#pragma unroll
        for (int i = 0; i < 8; i++) {
            uint32_t off = (uint32_t)t * 128u + i * 16u;
            uint32_t sw = off ^ ((off >> 3) & 0x70);
            *reinterpret_cast<uint4*>(sb + sw) = sH[i];
            *reinterpret_cast<uint4*>(sb + 16384 + sw) = sL[i];
        }
    }
    // B: threads 0-63 -> B_hi row t, 64-127 -> B_lo row t-64
    {
        const int r = t & 63;
        const __nv_bfloat16* src = (t < 64) ? Bhi : Blo;
        char* dst = sb + ((t < 64) ? 32768 : 40960);
        const int gn = n0 + r;
        if (gn < NB) {
            const uint4* s4 = reinterpret_cast<const uint4*>(src + (size_t)gn * K + k0);
#pragma unroll
            for (int i = 0; i < 8; i++) {
                uint32_t off = (uint32_t)r * 128u + i * 16u;
                uint32_t sw = off ^ ((off >> 3) & 0x70);
                *reinterpret_cast<uint4*>(dst + sw) = s4[i];
            }
        } else {
            uint4 z = make_uint4(0, 0, 0, 0);
#pragma unroll
            for (int i = 0; i < 8; i++) {
                uint32_t off = (uint32_t)r * 128u + i * 16u;
                uint32_t sw = off ^ ((off >> 3) & 0x70);
                *reinterpret_cast<uint4*>(dst + sw) = z;
            }
        }
    }
}

template <int MODE>
__device__ __forceinline__ void epi_elem(float r, int m, int n,
        const float* __restrict__ bias, const float* __restrict__ xproj,
        const float* __restrict__ hold, float* __restrict__ outF,
        __nv_bfloat16* __restrict__ outHi, __nv_bfloat16* __restrict__ outLo,
        float scale, int NB, int ldOut) {
    if (MODE == 0) {
        outF[(size_t)m * ldOut + n] = fmaf(r, scale, bias[n]);
    } else if (MODE == 1) {
        const size_t idx = (size_t)m * D_H + n;
        const float pre = xproj[idx] + r + bias[n];
        const float hn = 0.5f * hold[idx] + 0.5f * tanhf(pre);
        outF[idx] = hn;
        __nv_bfloat16 hb = __float2bfloat16(hn);
        outHi[idx] = hb;
        outLo[idx] = __float2bfloat16(hn - __bfloat162float(hb));
    } else {
        if (n < NB) outF[(size_t)m * ldOut + n] = r + bias[n];
    }
}

#if !TC_OK
// swizzled-smem bf16 read for the portable-PTX fallback path
__device__ __forceinline__ float rd_sw(const char* sb, int row, int col) {
    uint32_t off = (uint32_t)row * 128u + (uint32_t)col * 2u;
    uint32_t sw = off ^ ((off >> 3) & 0x70);
    return __bfloat162float(*reinterpret_cast<const __nv_bfloat16*>(sb + sw));
}
#endif

template <int MODE>
__global__ void __launch_bounds__(128)
gemm_tc(const __nv_bfloat16* __restrict__ Ahi, const __nv_bfloat16* __restrict__ Alo,
        const __nv_bfloat16* __restrict__ Bhi, const __nv_bfloat16* __restrict__ Blo,
        const float* __restrict__ bias,
        const float* __restrict__ xproj, const float* __restrict__ hold,
        float* __restrict__ outF,
        __nv_bfloat16* __restrict__ outHi, __nv_bfloat16* __restrict__ outLo,
        const float* __restrict__ scale_ptr, int K, int NB, int ldOut) {
    extern __shared__ char smem[];
    const int tid = threadIdx.x;
    const int m0 = blockIdx.y * 128;
    const int n0 = blockIdx.x * 64;
    const float scale = (MODE == 0) ? *scale_ptr : 1.0f;
    const int NC = K >> 6;   // 64-wide K chunks

#if TC_OK
    const uint32_t sbase = smem_u32(smem);
    const int wid = tid >> 5;

    if (tid == 0) { MBAR_INIT(sbase + 0, 1); MBAR_INIT(sbase + 8, 1); }
    if (wid == 0) { TC_ALLOC(sbase + 16, 128); TC_RELINQ(); }
    __syncthreads();
    uint32_t tm;
    asm volatile("ld.shared.b32 %0, [%1];" : "=r"(tm) : "r"(sbase + 16));

    int ph0 = 0, ph1 = 0;

    load_chunk(smem + 1024, 0, Ahi, Alo, Bhi, Blo, K, NB, m0, n0);
    FENCE_ASYNC();
    __syncthreads();

    for (int c = 0; c < NC; c++) {
        const int b = c & 1;
        if (wid == 0) {
            if (elect_one()) {
                const uint32_t sa = sbase + 1024 + b * STAGE_SZ;
                uint64_t ah = make_desc(sa + 0),     al = make_desc(sa + 16384);
                uint64_t bh = make_desc(sa + 32768), bl = make_desc(sa + 40960);
#pragma unroll
                for (int k = 0; k < 4; k++)
                    mma_f16_ss(tm, ah + 2 * k, bh + 2 * k, IDESC_128x64, (c > 0) || (k > 0));
#pragma unroll
                for (int k = 0; k < 4; k++)
                    mma_f16_ss(tm, ah + 2 * k, bl + 2 * k, IDESC_128x64, 1u);
#pragma unroll
                for (int k = 0; k < 4; k++)
                    mma_f16_ss(tm, al + 2 * k, bh + 2 * k, IDESC_128x64, 1u);
                TC_COMMIT(sbase + 8 * b);
            }
        }
        if (c + 1 < NC) {
            const int ob = b ^ 1;
            if (c >= 1) {            // wait chunk c-1's MMAs before overwriting its buffer
                if (ob == 0) { MBAR_WAIT(sbase + 0, ph0); ph0 ^= 1; }
                else         { MBAR_WAIT(sbase + 8, ph1); ph1 ^= 1; }
            }
            load_chunk(smem + 1024 + ob * STAGE_SZ, (c + 1) << 6,
                       Ahi, Alo, Bhi, Blo, K, NB, m0, n0);
            FENCE_ASYNC();
            __syncthreads();
        }
    }
    // drain last two commits
    {
        const int b2 = (NC - 2) & 1, b1 = (NC - 1) & 1;
        if (b2 == 0) { MBAR_WAIT(sbase + 0, ph0); ph0 ^= 1; } else { MBAR_WAIT(sbase + 8, ph1); ph1 ^= 1; }
        if (b1 == 0) { MBAR_WAIT(sbase + 0, ph0); ph0 ^= 1; } else { MBAR_WAIT(sbase + 8, ph1); ph1 ^= 1; }
    }
    TC_FENCE_AFTER();

    // epilogue: each warp reads its 32-lane subpartition, 64 cols
    uint32_t d0[32], d1[32];
    LDTM_X32(d0, tm);
    LDTM_X32(d1, tm + 32);
    TC_WAIT_LD();
    TC_FENCE_BEFORE();

    const int lane = tid & 31;
    const int m = m0 + wid * 32 + lane;
#pragma unroll 8
    for (int c = 0; c < 64; c++) {
        const float r = __uint_as_float(c < 32 ? d0[c] : d1[c - 32]);
        epi_elem<MODE>(r, m, n0 + c, bias, xproj, hold, outF, outHi, outLo,
                       scale, NB, ldOut);
    }

    __syncthreads();
    if (wid == 0) TC_DEALLOC(tm, 128);

#else  // ---------------- portable fallback: FFMA from the same smem tiles ----
    char* sb = smem + 1024;            // single stage
    const int tn4  = (tid & 15) << 2;  // 4 cols
    const int tm16 = (tid >> 4) << 4;  // 16 rows
    float acc[16][4] = {};

    for (int c = 0; c < NC; c++) {
        __syncthreads();
        load_chunk(sb, c << 6, Ahi, Alo, Bhi, Blo, K, NB, m0, n0);
        __syncthreads();
        for (int k = 0; k < 64; k++) {
            float bv[4];
#pragma unroll
            for (int j = 0; j < 4; j++)
                bv[j] = rd_sw(sb + 32768, tn4 + j, k) + rd_sw(sb + 40960, tn4 + j, k);
#pragma unroll
            for (int i = 0; i < 16; i++) {
                float av = rd_sw(sb, tm16 + i, k) + rd_sw(sb + 16384, tm16 + i, k);
#pragma unroll
                for (int j = 0; j < 4; j++)
                    acc[i][j] = fmaf(av, bv[j], acc[i][j]);
            }
        }
    }
#pragma unroll
    for (int i = 0; i < 16; i++)
#pragma unroll
        for (int j = 0; j < 4; j++)
            epi_elem<MODE>(acc[i][j], m0 + tm16 + i, n0 + tn4 + j,
                           bias, xproj, hold, outF, outHi, outLo, scale, NB, ldOut);
#endif
}

// ---------------- host ----------------
extern "C" void kernel_launch(void* const* d_in, const int* in_sizes, int n_in,
                              void* d_out, int out_size) {
    const float* x     = (const float*)d_in[0];
    const float* Winw  = (const float*)d_in[1];
    const float* Winb  = (const float*)d_in[2];
    const float* u     = (const float*)d_in[3];
    const float* W0    = (const float*)d_in[4];
    const float* b0    = (const float*)d_in[5];
    const float* W1    = (const float*)d_in[6];
    const float* b1    = (const float*)d_in[7];
    const float* W2    = (const float*)d_in[8];
    const float* b2    = (const float*)d_in[9];
    const float* headw = (const float*)d_in[10];
    const float* headb = (const float*)d_in[11];
    float* out = (float*)d_out;

    float *t, *s, *scal, *xp, *hA, *hB;
    cudaGetSymbolAddress((void**)&t, g_t);
    cudaGetSymbolAddress((void**)&s, g_s);
    cudaGetSymbolAddress((void**)&scal, g_scal);
    cudaGetSymbolAddress((void**)&xp, g_xproj);
    cudaGetSymbolAddress((void**)&hA, g_hA);
    cudaGetSymbolAddress((void**)&hB, g_hB);
    __nv_bfloat16 *W0h, *W0l, *W1h, *W1l, *W2h, *W2l, *Winh, *Winl, *Hdh, *Hdl;
    __nv_bfloat16 *xh, *xl, *hhA, *hlA, *hhB, *hlB;
    cudaGetSymbolAddress((void**)&W0h, g_W0hi);  cudaGetSymbolAddress((void**)&W0l, g_W0lo);
    cudaGetSymbolAddress((void**)&W1h, g_W1hi);  cudaGetSymbolAddress((void**)&W1l, g_W1lo);
    cudaGetSymbolAddress((void**)&W2h, g_W2hi);  cudaGetSymbolAddress((void**)&W2l, g_W2lo);
    cudaGetSymbolAddress((void**)&Winh, g_Winhi); cudaGetSymbolAddress((void**)&Winl, g_Winlo);
    cudaGetSymbolAddress((void**)&Hdh, g_Hdhi);  cudaGetSymbolAddress((void**)&Hdl, g_Hdlo);
    cudaGetSymbolAddress((void**)&xh, g_xhi);    cudaGetSymbolAddress((void**)&xl, g_xlo);
    cudaGetSymbolAddress((void**)&hhA, g_hhiA);  cudaGetSymbolAddress((void**)&hlA, g_hloA);
    cudaGetSymbolAddress((void**)&hhB, g_hhiB);  cudaGetSymbolAddress((void**)&hlB, g_hloB);

    cudaFuncSetAttribute(gemm_tc<0>, cudaFuncAttributeMaxDynamicSharedMemorySize, SMEM_BYTES);
    cudaFuncSetAttribute(gemm_tc<1>, cudaFuncAttributeMaxDynamicSharedMemorySize, SMEM_BYTES);
    cudaFuncSetAttribute(gemm_tc<2>, cudaFuncAttributeMaxDynamicSharedMemorySize, SMEM_BYTES);

    // h0 = 0 (fp32 + bf16 hi/lo)
    zero_kernel<<<(BATCH * D_H + 255) / 256, 256>>>(hA, BATCH * D_H);
    zero_kernel<<<(BATCH * D_H / 2 + 255) / 256, 256>>>((float*)hhA, BATCH * D_H / 2);
    zero_kernel<<<(BATCH * D_H / 2 + 255) / 256, 256>>>((float*)hlA, BATCH * D_H / 2);

    // hi/lo splits of all static operands
    const int TB = 256;
    split_kernel<<<(D_H * D_H + TB - 1) / TB, TB>>>(W0, W0h, W0l, D_H * D_H);
    split_kernel<<<(D_H * D_H + TB - 1) / TB, TB>>>(W1, W1h, W1l, D_H * D_H);
    split_kernel<<<(D_H * D_H + TB - 1) / TB, TB>>>(W2, W2h, W2l, D_H * D_H);
    split_kernel<<<(D_H * D_IN + TB - 1) / TB, TB>>>(Winw, Winh, Winl, D_H * D_IN);
    split_kernel<<<(D_OUT * D_H + TB - 1) / TB, TB>>>(headw, Hdh, Hdl, D_OUT * D_H);
    split_kernel<<<(BATCH * D_IN + TB - 1) / TB, TB>>>(x, xh, xl, BATCH * D_IN);

    // spectral-norm scalar -> g_scal[1]
    matvec_t_kernel<<<D_IN / 256, 256>>>(Winw, u, t);
    reduce_t_kernel<<<1, 1024>>>(t, scal);
    matvec_s_kernel<<<64, 256>>>(Winw, t, scal, s);
    reduce_s_kernel<<<1, 1024>>>(s, scal);

    // x_proj = (x @ W_in^T)/sigma + b_in
    {
        dim3 grid(D_H / 64, BATCH / 128);
        gemm_tc<0><<<grid, 128, SMEM_BYTES>>>(xh, xl, Winh, Winl, Winb,
                                              nullptr, nullptr, xp, nullptr, nullptr,
                                              scal + 1, D_IN, D_H, D_H);
    }

    // 30 steps x 3 layers
    const __nv_bfloat16* Wh[3] = {W0h, W1h, W2h};
    const __nv_bfloat16* Wl[3] = {W0l, W1l, W2l};
    const float* bs[3] = {b0, b1, b2};
    float *cur = hA, *nxt = hB;
    __nv_bfloat16 *curh = hhA, *curl = hlA, *nxth = hhB, *nxtl = hlB;
    dim3 gstep(D_H / 64, BATCH / 128);
    for (int st = 0; st < STEPS; st++) {
        for (int l = 0; l < 3; l++) {
            gemm_tc<1><<<gstep, 128, SMEM_BYTES>>>(curh, curl, Wh[l], Wl[l], bs[l],
                                                   xp, cur, nxt, nxth, nxtl,
                                                   nullptr, D_H, D_H, D_H);
            float* tf = cur; cur = nxt; nxt = tf;
            __nv_bfloat16* th = curh; curh = nxth; nxth = th;
            __nv_bfloat16* tl = curl; curl = nxtl; nxtl = tl;
        }
    }

    // head: out = h @ head_w^T + head_b
    {
        dim3 grid(16, BATCH / 128);   // 16*64 = 1024 cols cover 1000 (guarded)
        gemm_tc<2><<<grid, 128, SMEM_BYTES>>>(curh, curl, Hdh, Hdl, headb,
                                              nullptr, nullptr, out, nullptr, nullptr,
                                              nullptr, D_H, D_OUT, D_OUT);
    }
}

// round 5
// speedup vs baseline: 3.5062x; 3.5062x over previous
#include <cuda_runtime.h>
#include <cuda_bf16.h>
#include <math.h>
#include <stdint.h>

#define D_IN   1024
#define D_H    2048
#define BATCH  256
#define D_OUT  1000
#define EPSV   1e-12f
#define STEPS  30

// smem tile geometry: 64 rows x 64 bf16 (128B) padded to 144B/row
#define ROW_B      144
#define TILE_BYTES (64 * ROW_B)       // 9216
#define TILE_A_HI  0
#define TILE_A_LO  9216
#define TILE_B_HI  18432
#define TILE_B_LO  27648
#define STAGE_BYTES 36864
#define SMEM_BYTES  (2 * STAGE_BYTES) // 73728

// ---------------- device scratch (no allocations allowed) ----------------
__device__ float g_t[D_IN];
__device__ float g_s[D_H];
__device__ float g_scal[4];            // [1] = 1/sigma
__device__ float g_xproj[BATCH * D_H];
__device__ float g_hA[BATCH * D_H];
__device__ float g_hB[BATCH * D_H];

__device__ __nv_bfloat16 g_W0hi[D_H * D_H], g_W0lo[D_H * D_H];
__device__ __nv_bfloat16 g_W1hi[D_H * D_H], g_W1lo[D_H * D_H];
__device__ __nv_bfloat16 g_W2hi[D_H * D_H], g_W2lo[D_H * D_H];
__device__ __nv_bfloat16 g_Winhi[D_H * D_IN], g_Winlo[D_H * D_IN];
__device__ __nv_bfloat16 g_Hdhi[D_OUT * D_H], g_Hdlo[D_OUT * D_H];
__device__ __nv_bfloat16 g_xhi[BATCH * D_IN], g_xlo[BATCH * D_IN];
__device__ __nv_bfloat16 g_hhiA[BATCH * D_H], g_hloA[BATCH * D_H];
__device__ __nv_bfloat16 g_hhiB[BATCH * D_H], g_hloB[BATCH * D_H];

// ---------------- portable PTX helpers (sm_80+) ----------------
__device__ __forceinline__ uint32_t smem_u32(const void* p) {
    uint32_t a;
    asm("{ .reg .u64 t; cvta.to.shared.u64 t, %1; cvt.u32.u64 %0, t; }" : "=r"(a) : "l"(p));
    return a;
}
#define CP16(dst, src) asm volatile("cp.async.cg.shared.global [%0], [%1], 16;" :: "r"(dst), "l"(src))
#define CP_COMMIT()    asm volatile("cp.async.commit_group;" ::: "memory")
#define CP_WAIT(n)     asm volatile("cp.async.wait_group %0;" :: "n"(n) : "memory")

__device__ __forceinline__ void ldsm4(uint32_t* r, uint32_t addr) {
    asm volatile("ldmatrix.sync.aligned.m8n8.x4.shared.b16 {%0,%1,%2,%3}, [%4];"
        : "=r"(r[0]), "=r"(r[1]), "=r"(r[2]), "=r"(r[3]) : "r"(addr));
}
__device__ __forceinline__ void mma_bf16(float* c, const uint32_t* a, const uint32_t* b) {
    asm volatile("mma.sync.aligned.m16n8k16.row.col.f32.bf16.bf16.f32 "
        "{%0,%1,%2,%3}, {%4,%5,%6,%7}, {%8,%9}, {%0,%1,%2,%3};"
        : "+f"(c[0]), "+f"(c[1]), "+f"(c[2]), "+f"(c[3])
        : "r"(a[0]), "r"(a[1]), "r"(a[2]), "r"(a[3]), "r"(b[0]), "r"(b[1]));
}

// ---------------- small kernels ----------------
__global__ void zero_kernel(float* p, int n) {
    int i = blockIdx.x * blockDim.x + threadIdx.x;
    if (i < n) p[i] = 0.0f;
}
__global__ void split_kernel(const float* __restrict__ src,
                             __nv_bfloat16* __restrict__ hi,
                             __nv_bfloat16* __restrict__ lo, int n) {
    int i = blockIdx.x * blockDim.x + threadIdx.x;
    if (i >= n) return;
    float a = src[i];
    __nv_bfloat16 h = __float2bfloat16(a);
    hi[i] = h;
    lo[i] = __float2bfloat16(a - __bfloat162float(h));
}
__global__ void matvec_t_kernel(const float* __restrict__ W, const float* __restrict__ u,
                                float* __restrict__ t) {
    int j = blockIdx.x * blockDim.x + threadIdx.x;
    if (j >= D_IN) return;
    float acc = 0.0f;
#pragma unroll 4
    for (int i = 0; i < D_H; i++) acc = fmaf(W[(size_t)i * D_IN + j], u[i], acc);
    t[j] = acc;
}
__global__ void reduce_t_kernel(const float* __restrict__ t, float* __restrict__ scal) {
    __shared__ float sh[1024];
    int tid = threadIdx.x;
    float v = t[tid];
    sh[tid] = v * v;
    __syncthreads();
    for (int o = 512; o > 0; o >>= 1) { if (tid < o) sh[tid] += sh[tid + o]; __syncthreads(); }
    if (tid == 0) scal[0] = 1.0f / (sqrtf(sh[0]) + EPSV);
}
__global__ void matvec_s_kernel(const float* __restrict__ W, const float* __restrict__ t,
                                const float* __restrict__ scal, float* __restrict__ s) {
    int gtid = blockIdx.x * blockDim.x + threadIdx.x;
    int warp = gtid >> 5, lane = gtid & 31;
    float invn = scal[0];
    for (int r = warp; r < D_H; r += 512) {
        const float* row = W + (size_t)r * D_IN;
        float acc = 0.0f;
        for (int j = lane; j < D_IN; j += 32) acc = fmaf(row[j], t[j], acc);
#pragma unroll
        for (int o = 16; o > 0; o >>= 1) acc += __shfl_xor_sync(0xffffffffu, acc, o);
        if (lane == 0) s[r] = acc * invn;
    }
}
__global__ void reduce_s_kernel(const float* __restrict__ s, float* __restrict__ scal) {
    __shared__ float sh[1024];
    int tid = threadIdx.x;
    float a = s[tid], b = s[tid + 1024];
    sh[tid] = a * a + b * b;
    __syncthreads();
    for (int o = 512; o > 0; o >>= 1) { if (tid < o) sh[tid] += sh[tid + o]; __syncthreads(); }
    if (tid == 0) { float q = sh[0]; scal[1] = (sqrtf(q) + EPSV) / q; }
}

// ---------------- fused epilogue element ----------------
template <int MODE>
__device__ __forceinline__ void epi_elem(float r, int m, int n,
        const float* __restrict__ bias, const float* __restrict__ xproj,
        const float* __restrict__ hold, float* __restrict__ outF,
        __nv_bfloat16* __restrict__ outHi, __nv_bfloat16* __restrict__ outLo,
        float scale, int NB, int ldOut) {
    if (MODE == 0) {
        outF[(size_t)m * ldOut + n] = fmaf(r, scale, bias[n]);
    } else if (MODE == 1) {
        const size_t idx = (size_t)m * D_H + n;
        const float pre = xproj[idx] + r + bias[n];
        const float hn = 0.5f * hold[idx] + 0.5f * tanhf(pre);
        outF[idx] = hn;
        __nv_bfloat16 hb = __float2bfloat16(hn);
        outHi[idx] = hb;
        outLo[idx] = __float2bfloat16(hn - __bfloat162float(hb));
    } else {
        if (n < NB) outF[(size_t)m * ldOut + n] = r + bias[n];
    }
}

// ---------------- cp.async prefetch of one BK=64 chunk (4 tiles) ----------------
__device__ __forceinline__ void prefetch_chunk(uint32_t sb_u, char* sb_p, int k0,
        const __nv_bfloat16* __restrict__ Ahi, const __nv_bfloat16* __restrict__ Alo,
        const __nv_bfloat16* __restrict__ Bhi, const __nv_bfloat16* __restrict__ Blo,
        int K, int NB, int m0, int n0) {
    const int t = threadIdx.x;
#pragma unroll
    for (int r = 0; r < 4; r++) {
        const int idx = t + (r << 7);        // 0..511
        const int row = idx >> 3;
        const int c   = idx & 7;
        const uint32_t soff = (uint32_t)row * ROW_B + (c << 4);
        const size_t ga = (size_t)(m0 + row) * K + k0 + (c << 3);
        CP16(sb_u + TILE_A_HI + soff, Ahi + ga);
        CP16(sb_u + TILE_A_LO + soff, Alo + ga);
        const int gn = n0 + row;
        if (gn < NB) {
            const size_t gb = (size_t)gn * K + k0 + (c << 3);
            CP16(sb_u + TILE_B_HI + soff, Bhi + gb);
            CP16(sb_u + TILE_B_LO + soff, Blo + gb);
        } else {
            const uint4 z = make_uint4(0, 0, 0, 0);
            *reinterpret_cast<uint4*>(sb_p + TILE_B_HI + soff) = z;
            *reinterpret_cast<uint4*>(sb_p + TILE_B_LO + soff) = z;
        }
    }
}

// ---------------- mma.sync GEMM: C = (Ahi+Alo)(Bhi+Blo)^T (lo*lo dropped) ----
// CTA tile 64x64, 128 threads (4 warps, 2x2 of 32x32 warp tiles), BK=64,
// double-buffered cp.async. MODE semantics as in epi_elem.
template <int MODE>
__global__ void __launch_bounds__(128)
gemm_mma(const __nv_bfloat16* __restrict__ Ahi, const __nv_bfloat16* __restrict__ Alo,
         const __nv_bfloat16* __restrict__ Bhi, const __nv_bfloat16* __restrict__ Blo,
         const float* __restrict__ bias,
         const float* __restrict__ xproj, const float* __restrict__ hold,
         float* __restrict__ outF,
         __nv_bfloat16* __restrict__ outHi, __nv_bfloat16* __restrict__ outLo,
         const float* __restrict__ scale_ptr, int K, int NB, int ldOut) {
    extern __shared__ char smem[];
    const uint32_t sbase = smem_u32(smem);
    const int tid  = threadIdx.x;
    const int lane = tid & 31;
    const int wid  = tid >> 5;
    const int m0 = blockIdx.y * 64;
    const int n0 = blockIdx.x * 64;
    const int wm = (wid >> 1) << 5;   // warp row offset in CTA tile
    const int wn = (wid & 1) << 5;    // warp col offset
    const int NC = K >> 6;

    // ldmatrix lane->row/koff maps (x4, non-transposed 8x8 b16 tiles)
    const int arow  = (lane & 7) | (((lane >> 3) & 1) << 3);
    const int akoff = ((lane >> 4) & 1) << 3;
    const int brow  = (lane & 7) | (((lane >> 4) & 1) << 3);
    const int bkoff = ((lane >> 3) & 1) << 3;

    float acc[2][4][4] = {};

    prefetch_chunk(sbase, smem, 0, Ahi, Alo, Bhi, Blo, K, NB, m0, n0);
    CP_COMMIT();

    for (int c = 0; c < NC; c++) {
        if (c + 1 < NC) {
            const int ns = (c + 1) & 1;
            prefetch_chunk(sbase + ns * STAGE_BYTES, smem + ns * STAGE_BYTES,
                           (c + 1) << 6, Ahi, Alo, Bhi, Blo, K, NB, m0, n0);
            CP_COMMIT();
            CP_WAIT(1);
        } else {
            CP_WAIT(0);
        }
        __syncthreads();

        const uint32_t st = sbase + (c & 1) * STAGE_BYTES;
#pragma unroll
        for (int kk = 0; kk < 4; kk++) {
            const int k0 = kk << 4;
            uint32_t ah[2][4], al[2][4], bh[2][4], bl[2][4];
#pragma unroll
            for (int a = 0; a < 2; a++) {
                const uint32_t off = (uint32_t)(wm + (a << 4) + arow) * ROW_B +
                                     ((k0 + akoff) << 1);
                ldsm4(ah[a], st + TILE_A_HI + off);
                ldsm4(al[a], st + TILE_A_LO + off);
            }
#pragma unroll
            for (int b = 0; b < 2; b++) {
                const uint32_t off = (uint32_t)(wn + (b << 4) + brow) * ROW_B +
                                     ((k0 + bkoff) << 1);
                ldsm4(bh[b], st + TILE_B_HI + off);
                ldsm4(bl[b], st + TILE_B_LO + off);
            }
#pragma unroll
            for (int a = 0; a < 2; a++)
#pragma unroll
                for (int j = 0; j < 4; j++) {
                    const uint32_t* bhp = &bh[j >> 1][(j & 1) << 1];
                    const uint32_t* blp = &bl[j >> 1][(j & 1) << 1];
                    mma_bf16(acc[a][j], ah[a], bhp);
                    mma_bf16(acc[a][j], ah[a], blp);
                    mma_bf16(acc[a][j], al[a], bhp);
                }
        }
        __syncthreads();
    }

    // epilogue
    const float scale = (MODE == 0) ? *scale_ptr : 1.0f;
    const int g  = lane >> 2;
    const int i2 = (lane & 3) << 1;
#pragma unroll
    for (int a = 0; a < 2; a++)
#pragma unroll
        for (int j = 0; j < 4; j++)
#pragma unroll
            for (int e = 0; e < 4; e++) {
                const int m = m0 + wm + (a << 4) + g + ((e >> 1) << 3);
                const int n = n0 + wn + (j << 3) + i2 + (e & 1);
                epi_elem<MODE>(acc[a][j][e], m, n, bias, xproj, hold,
                               outF, outHi, outLo, scale, NB, ldOut);
            }
}

// ---------------- host ----------------
extern "C" void kernel_launch(void* const* d_in, const int* in_sizes, int n_in,
                              void* d_out, int out_size) {
    const float* x     = (const float*)d_in[0];
    const float* Winw  = (const float*)d_in[1];
    const float* Winb  = (const float*)d_in[2];
    const float* u     = (const float*)d_in[3];
    const float* W0    = (const float*)d_in[4];
    const float* b0    = (const float*)d_in[5];
    const float* W1    = (const float*)d_in[6];
    const float* b1    = (const float*)d_in[7];
    const float* W2    = (const float*)d_in[8];
    const float* b2    = (const float*)d_in[9];
    const float* headw = (const float*)d_in[10];
    const float* headb = (const float*)d_in[11];
    float* out = (float*)d_out;

    float *t, *s, *scal, *xp, *hA, *hB;
    cudaGetSymbolAddress((void**)&t, g_t);
    cudaGetSymbolAddress((void**)&s, g_s);
    cudaGetSymbolAddress((void**)&scal, g_scal);
    cudaGetSymbolAddress((void**)&xp, g_xproj);
    cudaGetSymbolAddress((void**)&hA, g_hA);
    cudaGetSymbolAddress((void**)&hB, g_hB);
    __nv_bfloat16 *W0h, *W0l, *W1h, *W1l, *W2h, *W2l, *Winh, *Winl, *Hdh, *Hdl;
    __nv_bfloat16 *xh, *xl, *hhA, *hlA, *hhB, *hlB;
    cudaGetSymbolAddress((void**)&W0h, g_W0hi);  cudaGetSymbolAddress((void**)&W0l, g_W0lo);
    cudaGetSymbolAddress((void**)&W1h, g_W1hi);  cudaGetSymbolAddress((void**)&W1l, g_W1lo);
    cudaGetSymbolAddress((void**)&W2h, g_W2hi);  cudaGetSymbolAddress((void**)&W2l, g_W2lo);
    cudaGetSymbolAddress((void**)&Winh, g_Winhi); cudaGetSymbolAddress((void**)&Winl, g_Winlo);
    cudaGetSymbolAddress((void**)&Hdh, g_Hdhi);  cudaGetSymbolAddress((void**)&Hdl, g_Hdlo);
    cudaGetSymbolAddress((void**)&xh, g_xhi);    cudaGetSymbolAddress((void**)&xl, g_xlo);
    cudaGetSymbolAddress((void**)&hhA, g_hhiA);  cudaGetSymbolAddress((void**)&hlA, g_hloA);
    cudaGetSymbolAddress((void**)&hhB, g_hhiB);  cudaGetSymbolAddress((void**)&hlB, g_hloB);

    cudaFuncSetAttribute(gemm_mma<0>, cudaFuncAttributeMaxDynamicSharedMemorySize, SMEM_BYTES);
    cudaFuncSetAttribute(gemm_mma<1>, cudaFuncAttributeMaxDynamicSharedMemorySize, SMEM_BYTES);
    cudaFuncSetAttribute(gemm_mma<2>, cudaFuncAttributeMaxDynamicSharedMemorySize, SMEM_BYTES);

    // h0 = 0 (fp32 + bf16 hi/lo views)
    zero_kernel<<<(BATCH * D_H + 255) / 256, 256>>>(hA, BATCH * D_H);
    zero_kernel<<<(BATCH * D_H / 2 + 255) / 256, 256>>>((float*)hhA, BATCH * D_H / 2);
    zero_kernel<<<(BATCH * D_H / 2 + 255) / 256, 256>>>((float*)hlA, BATCH * D_H / 2);

    // hi/lo splits of static operands
    const int TB = 256;
    split_kernel<<<(D_H * D_H + TB - 1) / TB, TB>>>(W0, W0h, W0l, D_H * D_H);
    split_kernel<<<(D_H * D_H + TB - 1) / TB, TB>>>(W1, W1h, W1l, D_H * D_H);
    split_kernel<<<(D_H * D_H + TB - 1) / TB, TB>>>(W2, W2h, W2l, D_H * D_H);
    split_kernel<<<(D_H * D_IN + TB - 1) / TB, TB>>>(Winw, Winh, Winl, D_H * D_IN);
    split_kernel<<<(D_OUT * D_H + TB - 1) / TB, TB>>>(headw, Hdh, Hdl, D_OUT * D_H);
    split_kernel<<<(BATCH * D_IN + TB - 1) / TB, TB>>>(x, xh, xl, BATCH * D_IN);

    // spectral-norm scalar -> g_scal[1]
    matvec_t_kernel<<<D_IN / 256, 256>>>(Winw, u, t);
    reduce_t_kernel<<<1, 1024>>>(t, scal);
    matvec_s_kernel<<<64, 256>>>(Winw, t, scal, s);
    reduce_s_kernel<<<1, 1024>>>(s, scal);

    // x_proj = (x @ W_in^T)/sigma + b_in
    {
        dim3 grid(D_H / 64, BATCH / 64);
        gemm_mma<0><<<grid, 128, SMEM_BYTES>>>(xh, xl, Winh, Winl, Winb,
                                               nullptr, nullptr, xp, nullptr, nullptr,
                                               scal + 1, D_IN, D_H, D_H);
    }

    // 30 steps x 3 layers, ping-pong h (fp32 + bf16 hi/lo)
    const __nv_bfloat16* Wh[3] = {W0h, W1h, W2h};
    const __nv_bfloat16* Wl[3] = {W0l, W1l, W2l};
    const float* bs[3] = {b0, b1, b2};
    float *cur = hA, *nxt = hB;
    __nv_bfloat16 *curh = hhA, *curl = hlA, *nxth = hhB, *nxtl = hlB;
    dim3 gstep(D_H / 64, BATCH / 64);
    for (int st = 0; st < STEPS; st++) {
        for (int l = 0; l < 3; l++) {
            gemm_mma<1><<<gstep, 128, SMEM_BYTES>>>(curh, curl, Wh[l], Wl[l], bs[l],
                                                    xp, cur, nxt, nxth, nxtl,
                                                    nullptr, D_H, D_H, D_H);
            float* tf = cur; cur = nxt; nxt = tf;
            __nv_bfloat16* th = curh; curh = nxth; nxth = th;
            __nv_bfloat16* tl = curl; curl = nxtl; nxtl = tl;
        }
    }

    // head: out = h @ head_w^T + head_b   (N=1000, padded tiles guarded)
    {
        dim3 grid((D_OUT + 63) / 64, BATCH / 64);
        gemm_mma<2><<<grid, 128, SMEM_BYTES>>>(curh, curl, Hdh, Hdl, headb,
                                               nullptr, nullptr, out, nullptr, nullptr,
                                               nullptr, D_H, D_OUT, D_OUT);
    }
}